// round 16
// baseline (speedup 1.0000x reference)
#include <cuda_runtime.h>
#include <cuda_bf16.h>
#include <cstdint>

#define B_   16
#define TE_  128
#define TD_  64
#define H_   256
#define OUT_ 32000

// ---------------- scratch (static device arrays; no runtime alloc) ----------------
__device__ float g_scratch[4460544];
__device__ __align__(16) __nv_bfloat16 g_Ahi[1024 * 256];
__device__ __align__(16) __nv_bfloat16 g_Alo[1024 * 256];
__device__ __align__(16) __nv_bfloat16 g_Bhi[32000 * 256];
__device__ __align__(16) __nv_bfloat16 g_Blo[32000 * 256];

// ---------------- fast math ----------------
__device__ __forceinline__ float fsig(float x) {
    return __fdividef(1.f, 1.f + __expf(-x));
}
__device__ __forceinline__ float ftanh(float x) {
    float e = __expf(2.f * x);
    return 1.f - __fdividef(2.f, e + 1.f);
}
__device__ __forceinline__ uint32_t su32(const void* p) {
    uint32_t a;
    asm("{ .reg .u64 t; cvta.to.shared.u64 t, %1; cvt.u32.u64 %0, t; }" : "=r"(a) : "l"(p));
    return a;
}

// ---------------- tiled SGEMM: C[m,n] = act( sum_k A[m,k]*B[n,k] + bias[n] ) ----------
template <int TM, int TN, int ACT>
__global__ void __launch_bounds__(256)
gemm_kernel(int M, int N, int K,
            const float* __restrict__ A, int lda, const int* __restrict__ gather,
            const float* __restrict__ Bm, int ldb, int boff,
            const float* __restrict__ bias,
            float* __restrict__ C, int ldc)
{
    constexpr int BM = 16 * TM, BN = 16 * TN;
    constexpr int CA = BM / 64, CB = BN / 64;
    __shared__ float As[16][BM];
    __shared__ float Bs[16][BN];
    const int bm = blockIdx.y * BM, bn = blockIdx.x * BN;
    const int tid = threadIdx.x;
    const int tx = tid & 15, ty = tid >> 4;

    const float* aptr[CA];
    const float* bptr[CB];
#pragma unroll
    for (int it = 0; it < CA; it++) {
        int idx = tid + it * 256, row = idx >> 2, k4 = idx & 3;
        int ar = bm + row;
        long g = gather ? (long)gather[ar] : (long)ar;
        aptr[it] = A + g * (long)lda + k4 * 4;
    }
#pragma unroll
    for (int it = 0; it < CB; it++) {
        int idx = tid + it * 256, row = idx >> 2, k4 = idx & 3;
        bptr[it] = Bm + (long)(bn + row) * ldb + boff + k4 * 4;
    }

    float acc[TM][TN];
#pragma unroll
    for (int i = 0; i < TM; i++)
#pragma unroll
        for (int j = 0; j < TN; j++) acc[i][j] = 0.f;

    for (int k0 = 0; k0 < K; k0 += 16) {
#pragma unroll
        for (int it = 0; it < CA; it++) {
            int idx = tid + it * 256, row = idx >> 2, k4 = idx & 3;
            float4 va = *(const float4*)(aptr[it] + k0);
            As[k4 * 4 + 0][row] = va.x; As[k4 * 4 + 1][row] = va.y;
            As[k4 * 4 + 2][row] = va.z; As[k4 * 4 + 3][row] = va.w;
        }
#pragma unroll
        for (int it = 0; it < CB; it++) {
            int idx = tid + it * 256, row = idx >> 2, k4 = idx & 3;
            float4 vb = *(const float4*)(bptr[it] + k0);
            Bs[k4 * 4 + 0][row] = vb.x; Bs[k4 * 4 + 1][row] = vb.y;
            Bs[k4 * 4 + 2][row] = vb.z; Bs[k4 * 4 + 3][row] = vb.w;
        }
        __syncthreads();
#pragma unroll
        for (int k = 0; k < 16; k++) {
            float a[TM], b[TN];
#pragma unroll
            for (int p = 0; p < TM / 4; p++)
                *(float4*)&a[4 * p] = *(const float4*)&As[k][ty * TM + 4 * p];
#pragma unroll
            for (int p = 0; p < TN / 4; p++)
                *(float4*)&b[4 * p] = *(const float4*)&Bs[k][tx * TN + 4 * p];
#pragma unroll
            for (int i = 0; i < TM; i++)
#pragma unroll
                for (int j = 0; j < TN; j++) acc[i][j] += a[i] * b[j];
        }
        __syncthreads();
    }

    float bv[TN];
#pragma unroll
    for (int j = 0; j < TN; j++) bv[j] = bias ? bias[bn + tx * TN + j] : 0.f;
#pragma unroll
    for (int i = 0; i < TM; i++) {
        long m = bm + ty * TM + i;
        float o[TN];
#pragma unroll
        for (int j = 0; j < TN; j++) {
            float v = acc[i][j] + bv[j];
            if (ACT) v = ftanh(v);
            o[j] = v;
        }
#pragma unroll
        for (int q = 0; q < TN / 4; q++)
            *(float4*)(C + m * (long)ldc + bn + tx * TN + 4 * q) = *(float4*)&o[4 * q];
    }
}

// ---------------- fp32 -> bf16 hi/lo split ----------------
__global__ void __launch_bounds__(256)
split_kernel(const float* __restrict__ x, __nv_bfloat16* __restrict__ hi,
             __nv_bfloat16* __restrict__ lo, int n4)
{
    int i = blockIdx.x * 256 + threadIdx.x;
    if (i >= n4) return;
    float4 v = ((const float4*)x)[i];
    float vv[4] = {v.x, v.y, v.z, v.w};
    __nv_bfloat16 h[4], l[4];
#pragma unroll
    for (int j = 0; j < 4; j++) {
        h[j] = __float2bfloat16(vv[j]);
        l[j] = __float2bfloat16(vv[j] - __bfloat162float(h[j]));
    }
    *(uint2*)(hi + 4 * (long)i) = *(uint2*)h;
    *(uint2*)(lo + 4 * (long)i) = *(uint2*)l;
}

// ---------------- logits GEMM via mma.sync bf16 (3-term split, fp32 accum) -------------
__global__ void __launch_bounds__(256)
logits_mma_kernel(const __nv_bfloat16* __restrict__ Ahi, const __nv_bfloat16* __restrict__ Alo,
                  const __nv_bfloat16* __restrict__ Bhi, const __nv_bfloat16* __restrict__ Blo,
                  const float* __restrict__ bias, float* __restrict__ C)
{
    __shared__ __nv_bfloat16 As[2][128 * 40];
    __shared__ __nv_bfloat16 Bs[2][128 * 40];
    __shared__ float bias_s[128];

    const int bn = blockIdx.x * 128, bm = blockIdx.y * 128;
    const int tid = threadIdx.x;
    const int wid = tid >> 5, lane = tid & 31;
    const int wm = wid >> 2, wn = wid & 3;
    const int g = lane >> 2, t = lane & 3;

    if (tid < 128) bias_s[tid] = bias[bn + tid];

    const int ra0 = tid >> 2, ua0 = tid & 3;
    const int ra1 = (tid + 256) >> 2, ua1 = (tid + 256) & 3;

    float acc[4][4][4];
#pragma unroll
    for (int mt = 0; mt < 4; mt++)
#pragma unroll
        for (int nt = 0; nt < 4; nt++)
#pragma unroll
            for (int q = 0; q < 4; q++) acc[mt][nt][q] = 0.f;

    uint4 r0_, r1_, r2_, r3_;
    {
        r0_ = *(const uint4*)(Ahi + (long)(bm + ra0) * 256 + ua0 * 8);
        r1_ = *(const uint4*)(Ahi + (long)(bm + ra1) * 256 + ua1 * 8);
        r2_ = *(const uint4*)(Bhi + (long)(bn + ra0) * 256 + ua0 * 8);
        r3_ = *(const uint4*)(Bhi + (long)(bn + ra1) * 256 + ua1 * 8);
    }
    *(uint4*)&As[0][ra0 * 40 + ua0 * 8] = r0_;
    *(uint4*)&As[0][ra1 * 40 + ua1 * 8] = r1_;
    *(uint4*)&Bs[0][ra0 * 40 + ua0 * 8] = r2_;
    *(uint4*)&Bs[0][ra1 * 40 + ua1 * 8] = r3_;
    __syncthreads();

    for (int s = 0; s < 24; s++) {
        const int buf = s & 1;
        uint4 n0, n1, n2, n3;
        if (s < 23) {
            int sn = s + 1;
            int term = sn >> 3, k0 = (sn & 7) * 32;
            const __nv_bfloat16* Asrc = (term < 2) ? Ahi : Alo;
            const __nv_bfloat16* Bsrc = (term == 1) ? Blo : Bhi;
            n0 = *(const uint4*)(Asrc + (long)(bm + ra0) * 256 + k0 + ua0 * 8);
            n1 = *(const uint4*)(Asrc + (long)(bm + ra1) * 256 + k0 + ua1 * 8);
            n2 = *(const uint4*)(Bsrc + (long)(bn + ra0) * 256 + k0 + ua0 * 8);
            n3 = *(const uint4*)(Bsrc + (long)(bn + ra1) * 256 + k0 + ua1 * 8);
        }

        const __nv_bfloat16* Ab = As[buf];
        const __nv_bfloat16* Bb = Bs[buf];
#pragma unroll
        for (int k16 = 0; k16 < 2; k16++) {
            const int kb = k16 * 16;
            uint32_t af[4][4], bf[4][2];
#pragma unroll
            for (int mt = 0; mt < 4; mt++) {
                int rr = wm * 64 + mt * 16 + g;
                af[mt][0] = *(const uint32_t*)(Ab + rr * 40 + kb + 2 * t);
                af[mt][1] = *(const uint32_t*)(Ab + (rr + 8) * 40 + kb + 2 * t);
                af[mt][2] = *(const uint32_t*)(Ab + rr * 40 + kb + 8 + 2 * t);
                af[mt][3] = *(const uint32_t*)(Ab + (rr + 8) * 40 + kb + 8 + 2 * t);
            }
#pragma unroll
            for (int nt = 0; nt < 4; nt++) {
                int cc = wn * 32 + nt * 8 + g;
                bf[nt][0] = *(const uint32_t*)(Bb + cc * 40 + kb + 2 * t);
                bf[nt][1] = *(const uint32_t*)(Bb + cc * 40 + kb + 8 + 2 * t);
            }
#pragma unroll
            for (int mt = 0; mt < 4; mt++)
#pragma unroll
                for (int nt = 0; nt < 4; nt++)
                    asm volatile(
                        "mma.sync.aligned.m16n8k16.row.col.f32.bf16.bf16.f32 "
                        "{%0,%1,%2,%3}, {%4,%5,%6,%7}, {%8,%9}, {%0,%1,%2,%3};"
                        : "+f"(acc[mt][nt][0]), "+f"(acc[mt][nt][1]),
                          "+f"(acc[mt][nt][2]), "+f"(acc[mt][nt][3])
                        : "r"(af[mt][0]), "r"(af[mt][1]), "r"(af[mt][2]), "r"(af[mt][3]),
                          "r"(bf[nt][0]), "r"(bf[nt][1]));
        }

        if (s < 23) {
            const int nb = buf ^ 1;
            *(uint4*)&As[nb][ra0 * 40 + ua0 * 8] = n0;
            *(uint4*)&As[nb][ra1 * 40 + ua1 * 8] = n1;
            *(uint4*)&Bs[nb][ra0 * 40 + ua0 * 8] = n2;
            *(uint4*)&Bs[nb][ra1 * 40 + ua1 * 8] = n3;
        }
        __syncthreads();
    }

#pragma unroll
    for (int mt = 0; mt < 4; mt++) {
        long row0 = bm + wm * 64 + mt * 16 + g;
#pragma unroll
        for (int nt = 0; nt < 4; nt++) {
            int cl = wn * 32 + nt * 8 + 2 * t;
            float2 v0 = make_float2(acc[mt][nt][0] + bias_s[cl],
                                    acc[mt][nt][1] + bias_s[cl + 1]);
            float2 v1 = make_float2(acc[mt][nt][2] + bias_s[cl],
                                    acc[mt][nt][3] + bias_s[cl + 1]);
            *(float2*)(C + row0 * OUT_ + bn + cl)       = v0;
            *(float2*)(C + (row0 + 8) * OUT_ + bn + cl) = v1;
        }
    }
}

// ---------------- persistent GRU: R15 structure, DSMEM release-counter sync ------------
// Cluster of 8 CTAs per batch element; CTA c owns hidden units [c*32, c*32+32).
// Whh slice in SMEM (rows padded to 260 floats). h double-buffered; gate lanes multicast
// new h via st.relaxed.cluster, then (after __syncwarp) lanes 0..7 red.release.cluster
// +1 to every CTA's counter. Consumers spin on their LOCAL counter with
// ld.acquire.cluster (29-cyc LDS poll instead of ~490-cyc barrier.cluster release).
// Single-phase-ahead double buffering is race-free: a CTA enters step t only after all
// peers published h_t, i.e. all finished reading the buffer about to be overwritten.
__global__ void __launch_bounds__(128) __cluster_dims__(8, 1, 1)
gru_kernel(const float* __restrict__ gi, const float* __restrict__ Whh,
           const float* __restrict__ bhh, const int* __restrict__ lengths,
           const float* __restrict__ h0, float* __restrict__ outp, int ostride,
           float* __restrict__ hT, int T)
{
    extern __shared__ float sm[];
    float* Wsh  = sm;                 // 96*260
    float* hb0  = sm + 96 * 260;      // 256
    float* hb1  = hb0 + 256;          // 256
    float* gh_s = hb1 + 256;          // 96
    float* bg_s = gh_s + 96;          // 96
    unsigned int* cnt = (unsigned int*)(bg_s + 96);

    const int c = blockIdx.x;         // cluster rank
    const int b = blockIdx.y;
    const int tid = threadIdx.x;
    const int len = lengths[b];

    for (int i = tid; i < 96 * 256; i += 128) {
        int r = i >> 8, k = i & 255;
        int grow = (r >> 5) * 256 + c * 32 + (r & 31);
        Wsh[r * 260 + k] = Whh[grow * 256 + k];
    }
    if (tid < 96) {
        int grow = (tid >> 5) * 256 + c * 32 + (tid & 31);
        bg_s[tid] = bhh[grow];
    }
    for (int j = tid; j < 256; j += 128)
        hb0[j] = h0 ? h0[b * 256 + j] : 0.f;
    if (tid == 0) *cnt = 0u;
    __syncthreads();

    // counters + buffers must be visible cluster-wide before any remote store/red
    asm volatile("barrier.cluster.arrive.aligned;\n" ::: "memory");
    asm volatile("barrier.cluster.wait.aligned;\n" ::: "memory");

    const int idx = c * 32 + (tid & 31);
    const uint32_t cnt_addr = su32(cnt);

    // prefetch gi for step 0
    float gir = 0.f, giz = 0.f, gin = 0.f;
    if (tid < 32) {
        long base = ((long)(b * T)) * 768;
        gir = gi[base + idx];
        giz = gi[base + 256 + idx];
        gin = gi[base + 512 + idx];
    }

    for (int t = 0; t < T; t++) {
        float* hcur = (t & 1) ? hb1 : hb0;
        float* hnxt = (t & 1) ? hb0 : hb1;

        if (t > 0) {
            unsigned target = 8u * (unsigned)t;
            unsigned v;
            do {
                asm volatile("ld.acquire.cluster.shared::cta.u32 %0, [%1];"
                             : "=r"(v) : "r"(cnt_addr) : "memory");
            } while (v < target);
        }

        if (tid < 96) {
            const float4* wr = (const float4*)(Wsh + tid * 260);
            const float4* hp = (const float4*)hcur;
            float a0 = 0.f, a1 = 0.f, a2 = 0.f, a3 = 0.f;
#pragma unroll
            for (int k = 0; k < 64; k++) {
                float4 w = wr[k]; float4 h4 = hp[k];
                a0 += w.x * h4.x; a1 += w.y * h4.y;
                a2 += w.z * h4.z; a3 += w.w * h4.w;
            }
            gh_s[tid] = (a0 + a1) + (a2 + a3) + bg_s[tid];
        }
        __syncthreads();

        if (tid < 32) {
            float rg = fsig(gir + gh_s[tid]);
            float zg = fsig(giz + gh_s[32 + tid]);
            float ng = ftanh(gin + rg * gh_s[64 + tid]);
            float hold = hcur[idx];
            float hnew = (1.f - zg) * ng + zg * hold;
            bool valid = (t < len);
            float hsel = valid ? hnew : hold;
            outp[((long)(b * T + t)) * ostride + idx] = valid ? hnew : 0.f;
            if (hT && t == T - 1) hT[b * 256 + idx] = hsel;

            uint32_t laddr = su32(&hnxt[idx]);
#pragma unroll
            for (int tc = 0; tc < 8; tc++) {
                uint32_t raddr;
                asm volatile("mapa.shared::cluster.u32 %0, %1, %2;"
                             : "=r"(raddr) : "r"(laddr), "r"(tc));
                asm volatile("st.relaxed.cluster.shared::cluster.f32 [%0], %1;"
                             :: "r"(raddr), "f"(hsel) : "memory");
            }
            // prefetch gi for step t+1 (hides DRAM latency under peers' spin/dot)
            if (t + 1 < T) {
                long base = ((long)(b * T + t + 1)) * 768;
                gir = gi[base + idx];
                giz = gi[base + 256 + idx];
                gin = gi[base + 512 + idx];
            }
            __syncwarp();
            if (tid < 8) {
                uint32_t rc;
                asm volatile("mapa.shared::cluster.u32 %0, %1, %2;"
                             : "=r"(rc) : "r"(cnt_addr), "r"(tid));
                asm volatile("red.release.cluster.shared::cluster.add.u32 [%0], %1;"
                             :: "r"(rc), "r"(1u) : "memory");
            }
        }
    }

    // SMEM lifetime: no CTA may exit while peers can still write into its SMEM
    asm volatile("barrier.cluster.arrive.aligned;\n" ::: "memory");
    asm volatile("barrier.cluster.wait.aligned;\n" ::: "memory");
}

// ---------------- fused attention: energies -> softmax(valid) -> context ----------------
__global__ void __launch_bounds__(256)
attn_kernel(const float* __restrict__ Penc, const float* __restrict__ Pdec,
            const float* __restrict__ enc_out, const float* __restrict__ av,
            const float* __restrict__ avb, const int* __restrict__ elen_p,
            const int* __restrict__ dlen_p, float* __restrict__ cat)
{
    const int b = blockIdx.y, td = blockIdx.x;
    const int tid = threadIdx.x;
    const long row = (long)b * TD_ + td;

    if (td >= dlen_p[b]) {
        cat[row * 512 + 256 + tid] = 0.f;
        return;
    }
    __shared__ float Pd_s[256], v_s[256], e_s[128], red_s[16];
    Pd_s[tid] = Pdec[row * 256 + tid];
    v_s[tid]  = av[tid];
    const int elen = elen_p[b];
    const float vb = avb[0];
    __syncthreads();

    const int warp = tid >> 5, lane = tid & 31;
    for (int te = warp; te < elen; te += 8) {
        const float* pe = Penc + ((long)b * TE_ + te) * 256;
        float s = 0.f;
#pragma unroll
        for (int j = 0; j < 8; j++) {
            int h = lane + j * 32;
            s += ftanh(pe[h] + Pd_s[h]) * v_s[h];
        }
#pragma unroll
        for (int o = 16; o; o >>= 1) s += __shfl_xor_sync(0xffffffffu, s, o);
        if (lane == 0) e_s[te] = s + vb;
    }
    __syncthreads();

    float x = (tid < elen) ? e_s[tid] : -1e30f;
    float m = x;
#pragma unroll
    for (int o = 16; o; o >>= 1) m = fmaxf(m, __shfl_xor_sync(0xffffffffu, m, o));
    if (lane == 0) red_s[warp] = m;
    __syncthreads();
    float mx = red_s[0];
#pragma unroll
    for (int i = 1; i < 8; i++) mx = fmaxf(mx, red_s[i]);

    float p = (tid < elen) ? __expf(x - mx) : 0.f;
    float ps = p;
#pragma unroll
    for (int o = 16; o; o >>= 1) ps += __shfl_xor_sync(0xffffffffu, ps, o);
    if (lane == 0) red_s[8 + warp] = ps;
    __syncthreads();
    float sum = 0.f;
#pragma unroll
    for (int i = 0; i < 8; i++) sum += red_s[8 + i];
    float inv = __fdividef(1.f, sum);
    if (tid < 128) e_s[tid] = p * inv;
    __syncthreads();

    float acc = 0.f;
    const float* eo = enc_out + ((long)b * TE_) * 256 + tid;
    int te = 0;
    for (; te + 4 <= elen; te += 4) {
        acc += e_s[te]     * eo[(long)te * 256];
        acc += e_s[te + 1] * eo[(long)(te + 1) * 256];
        acc += e_s[te + 2] * eo[(long)(te + 2) * 256];
        acc += e_s[te + 3] * eo[(long)(te + 3) * 256];
    }
    for (; te < elen; te++) acc += e_s[te] * eo[(long)te * 256];
    cat[row * 512 + 256 + tid] = acc;
}

// ---------------- launch ----------------
extern "C" void kernel_launch(void* const* d_in, const int* in_sizes, int n_in,
                              void* d_out, int out_size)
{
    (void)in_sizes; (void)n_in; (void)out_size;
    const int*   enc_in  = (const int*)d_in[0];
    const int*   enc_len = (const int*)d_in[1];
    const int*   dec_in  = (const int*)d_in[2];
    const int*   dec_len = (const int*)d_in[3];
    const float* emb     = (const float*)d_in[4];
    const float* eWih = (const float*)d_in[5];
    const float* eWhh = (const float*)d_in[6];
    const float* ebih = (const float*)d_in[7];
    const float* ebhh = (const float*)d_in[8];
    const float* dWih = (const float*)d_in[9];
    const float* dWhh = (const float*)d_in[10];
    const float* dbih = (const float*)d_in[11];
    const float* dbhh = (const float*)d_in[12];
    const float* aW   = (const float*)d_in[13];
    const float* aWb  = (const float*)d_in[14];
    const float* av   = (const float*)d_in[15];
    const float* avb  = (const float*)d_in[16];
    const float* dnW  = (const float*)d_in[17];
    const float* dnb  = (const float*)d_in[18];
    const float* oW   = (const float*)d_in[19];
    const float* ob   = (const float*)d_in[20];
    float* out = (float*)d_out;

    float* S = nullptr;
    cudaGetSymbolAddress((void**)&S, g_scratch);
    __nv_bfloat16 *Ahi, *Alo, *Bhi, *Blo;
    cudaGetSymbolAddress((void**)&Ahi, g_Ahi);
    cudaGetSymbolAddress((void**)&Alo, g_Alo);
    cudaGetSymbolAddress((void**)&Bhi, g_Bhi);
    cudaGetSymbolAddress((void**)&Blo, g_Blo);

    float* enc_gi  = S;
    float* dec_gi  = S + 1572864;
    float* enc_out = S + 2359296;
    float* enc_hT  = S + 2883584;
    float* cat     = S + 2887680;
    float* Penc    = S + 3411968;
    float* Pdec    = S + 3936256;
    float* dense   = S + 4198400;

    const size_t gru_smem = (96 * 260 + 256 + 256 + 96 + 96 + 4) * sizeof(float);
    cudaFuncSetAttribute(gru_kernel, cudaFuncAttributeMaxDynamicSharedMemorySize,
                         (int)gru_smem);

    // split out_W into bf16 hi/lo (independent; runs up front)
    split_kernel<<<(OUT_ * H_ / 4 + 255) / 256, 256>>>(oW, Bhi, Blo, OUT_ * H_ / 4);

    // gi pre-GEMMs (embedding gather fused), 64x64 tiles
    gemm_kernel<4, 4, 0><<<dim3(12, 32), 256>>>(2048, 768, 256, emb, 256, enc_in,
                                                eWih, 256, 0, ebih, enc_gi, 768);
    gemm_kernel<4, 4, 0><<<dim3(12, 16), 256>>>(1024, 768, 256, emb, 256, dec_in,
                                                dWih, 256, 0, dbih, dec_gi, 768);

    // encoder GRU (persistent, 16 clusters x 8 CTAs, DSMEM counter sync)
    gru_kernel<<<dim3(8, 16), 128, gru_smem>>>(enc_gi, eWhh, ebhh, enc_len,
                                               nullptr, enc_out, 256, enc_hT, TE_);

    // Penc = enc_out @ attn_W[:, :256]^T
    gemm_kernel<4, 4, 0><<<dim3(4, 32), 256>>>(2048, 256, 256, enc_out, 256, nullptr,
                                               aW, 512, 0, nullptr, Penc, 256);

    // decoder GRU -> cat[:, 0:256]
    gru_kernel<<<dim3(8, 16), 128, gru_smem>>>(dec_gi, dWhh, dbhh, dec_len,
                                               enc_hT, cat, 512, nullptr, TD_);

    // Pdec = dec_out @ attn_W[:, 256:512]^T + attn_Wb
    gemm_kernel<4, 4, 0><<<dim3(4, 16), 256>>>(1024, 256, 256, cat, 512, nullptr,
                                               aW, 512, 256, aWb, Pdec, 256);

    // fused attention -> cat[:, 256:512]
    attn_kernel<<<dim3(TD_, B_), 256>>>(Penc, Pdec, enc_out, av, avb,
                                        enc_len, dec_len, cat);

    // dense = tanh(cat @ dense_W^T + dense_b)
    gemm_kernel<4, 4, 1><<<dim3(4, 16), 256>>>(1024, 256, 512, cat, 512, nullptr,
                                               dnW, 512, 0, dnb, dense, 256);

    // split dense into bf16 hi/lo
    split_kernel<<<(1024 * 256 / 4 + 255) / 256, 256>>>(dense, Ahi, Alo, 1024 * 256 / 4);

    // logits = dense @ out_W^T + out_b via bf16 mma.sync (3-term split)
    logits_mma_kernel<<<dim3(250, 8), 256>>>(Ahi, Alo, Bhi, Blo, ob, out);
}

// round 17
// speedup vs baseline: 1.0895x; 1.0895x over previous
#include <cuda_runtime.h>
#include <cuda_bf16.h>
#include <cstdint>

#define B_   16
#define TE_  128
#define TD_  64
#define H_   256
#define OUT_ 32000

// ---------------- scratch (static device arrays; no runtime alloc) ----------------
__device__ float g_scratch[4460544];
__device__ __align__(16) __nv_bfloat16 g_Ahi[1024 * 256];
__device__ __align__(16) __nv_bfloat16 g_Alo[1024 * 256];
__device__ __align__(16) __nv_bfloat16 g_Bhi[32000 * 256];
__device__ __align__(16) __nv_bfloat16 g_Blo[32000 * 256];

// ---------------- fast math ----------------
__device__ __forceinline__ float fsig(float x) {
    return __fdividef(1.f, 1.f + __expf(-x));
}
__device__ __forceinline__ float ftanh(float x) {
    float e = __expf(2.f * x);
    return 1.f - __fdividef(2.f, e + 1.f);
}
__device__ __forceinline__ uint32_t su32(const void* p) {
    uint32_t a;
    asm("{ .reg .u64 t; cvta.to.shared.u64 t, %1; cvt.u32.u64 %0, t; }" : "=r"(a) : "l"(p));
    return a;
}

// ---------------- tiled SGEMM: C[m,n] = act( sum_k A[m,k]*B[n,k] + bias[n] ) ----------
// SPLIT=1: instead of fp32 C, write bf16 hi/lo decomposition (fused split epilogue).
template <int TM, int TN, int ACT, int SPLIT>
__global__ void __launch_bounds__(256)
gemm_kernel(int M, int N, int K,
            const float* __restrict__ A, int lda, const int* __restrict__ gather,
            const float* __restrict__ Bm, int ldb, int boff,
            const float* __restrict__ bias,
            float* __restrict__ C, int ldc,
            __nv_bfloat16* __restrict__ Ohi, __nv_bfloat16* __restrict__ Olo)
{
    constexpr int BM = 16 * TM, BN = 16 * TN;
    constexpr int CA = BM / 64, CB = BN / 64;
    __shared__ float As[16][BM];
    __shared__ float Bs[16][BN];
    const int bm = blockIdx.y * BM, bn = blockIdx.x * BN;
    const int tid = threadIdx.x;
    const int tx = tid & 15, ty = tid >> 4;

    const float* aptr[CA];
    const float* bptr[CB];
#pragma unroll
    for (int it = 0; it < CA; it++) {
        int idx = tid + it * 256, row = idx >> 2, k4 = idx & 3;
        int ar = bm + row;
        long g = gather ? (long)gather[ar] : (long)ar;
        aptr[it] = A + g * (long)lda + k4 * 4;
    }
#pragma unroll
    for (int it = 0; it < CB; it++) {
        int idx = tid + it * 256, row = idx >> 2, k4 = idx & 3;
        bptr[it] = Bm + (long)(bn + row) * ldb + boff + k4 * 4;
    }

    float acc[TM][TN];
#pragma unroll
    for (int i = 0; i < TM; i++)
#pragma unroll
        for (int j = 0; j < TN; j++) acc[i][j] = 0.f;

    for (int k0 = 0; k0 < K; k0 += 16) {
#pragma unroll
        for (int it = 0; it < CA; it++) {
            int idx = tid + it * 256, row = idx >> 2, k4 = idx & 3;
            float4 va = *(const float4*)(aptr[it] + k0);
            As[k4 * 4 + 0][row] = va.x; As[k4 * 4 + 1][row] = va.y;
            As[k4 * 4 + 2][row] = va.z; As[k4 * 4 + 3][row] = va.w;
        }
#pragma unroll
        for (int it = 0; it < CB; it++) {
            int idx = tid + it * 256, row = idx >> 2, k4 = idx & 3;
            float4 vb = *(const float4*)(bptr[it] + k0);
            Bs[k4 * 4 + 0][row] = vb.x; Bs[k4 * 4 + 1][row] = vb.y;
            Bs[k4 * 4 + 2][row] = vb.z; Bs[k4 * 4 + 3][row] = vb.w;
        }
        __syncthreads();
#pragma unroll
        for (int k = 0; k < 16; k++) {
            float a[TM], b[TN];
#pragma unroll
            for (int p = 0; p < TM / 4; p++)
                *(float4*)&a[4 * p] = *(const float4*)&As[k][ty * TM + 4 * p];
#pragma unroll
            for (int p = 0; p < TN / 4; p++)
                *(float4*)&b[4 * p] = *(const float4*)&Bs[k][tx * TN + 4 * p];
#pragma unroll
            for (int i = 0; i < TM; i++)
#pragma unroll
                for (int j = 0; j < TN; j++) acc[i][j] += a[i] * b[j];
        }
        __syncthreads();
    }

    float bv[TN];
#pragma unroll
    for (int j = 0; j < TN; j++) bv[j] = bias ? bias[bn + tx * TN + j] : 0.f;
#pragma unroll
    for (int i = 0; i < TM; i++) {
        long m = bm + ty * TM + i;
        float o[TN];
#pragma unroll
        for (int j = 0; j < TN; j++) {
            float v = acc[i][j] + bv[j];
            if (ACT) v = ftanh(v);
            o[j] = v;
        }
        if (SPLIT) {
            __nv_bfloat16 h8[TN], l8[TN];
#pragma unroll
            for (int j = 0; j < TN; j++) {
                h8[j] = __float2bfloat16(o[j]);
                l8[j] = __float2bfloat16(o[j] - __bfloat162float(h8[j]));
            }
#pragma unroll
            for (int q = 0; q < TN / 4; q++) {
                *(uint2*)(Ohi + m * (long)ldc + bn + tx * TN + 4 * q) = *(uint2*)&h8[4 * q];
                *(uint2*)(Olo + m * (long)ldc + bn + tx * TN + 4 * q) = *(uint2*)&l8[4 * q];
            }
        } else {
#pragma unroll
            for (int q = 0; q < TN / 4; q++)
                *(float4*)(C + m * (long)ldc + bn + tx * TN + 4 * q) = *(float4*)&o[4 * q];
        }
    }
}

// ---------------- fp32 -> bf16 hi/lo split (weights) ----------------
__global__ void __launch_bounds__(256)
split_kernel(const float* __restrict__ x, __nv_bfloat16* __restrict__ hi,
             __nv_bfloat16* __restrict__ lo, int n4)
{
    int i = blockIdx.x * 256 + threadIdx.x;
    if (i >= n4) return;
    float4 v = ((const float4*)x)[i];
    float vv[4] = {v.x, v.y, v.z, v.w};
    __nv_bfloat16 h[4], l[4];
#pragma unroll
    for (int j = 0; j < 4; j++) {
        h[j] = __float2bfloat16(vv[j]);
        l[j] = __float2bfloat16(vv[j] - __bfloat162float(h[j]));
    }
    *(uint2*)(hi + 4 * (long)i) = *(uint2*)h;
    *(uint2*)(lo + 4 * (long)i) = *(uint2*)l;
}

// ---------------- logits GEMM via mma.sync bf16 (3-term split, fp32 accum) -------------
__global__ void __launch_bounds__(256)
logits_mma_kernel(const __nv_bfloat16* __restrict__ Ahi, const __nv_bfloat16* __restrict__ Alo,
                  const __nv_bfloat16* __restrict__ Bhi, const __nv_bfloat16* __restrict__ Blo,
                  const float* __restrict__ bias, float* __restrict__ C)
{
    __shared__ __nv_bfloat16 As[2][128 * 40];
    __shared__ __nv_bfloat16 Bs[2][128 * 40];
    __shared__ float bias_s[128];

    const int bn = blockIdx.x * 128, bm = blockIdx.y * 128;
    const int tid = threadIdx.x;
    const int wid = tid >> 5, lane = tid & 31;
    const int wm = wid >> 2, wn = wid & 3;
    const int g = lane >> 2, t = lane & 3;

    if (tid < 128) bias_s[tid] = bias[bn + tid];

    const int ra0 = tid >> 2, ua0 = tid & 3;
    const int ra1 = (tid + 256) >> 2, ua1 = (tid + 256) & 3;

    float acc[4][4][4];
#pragma unroll
    for (int mt = 0; mt < 4; mt++)
#pragma unroll
        for (int nt = 0; nt < 4; nt++)
#pragma unroll
            for (int q = 0; q < 4; q++) acc[mt][nt][q] = 0.f;

    uint4 r0_, r1_, r2_, r3_;
    {
        r0_ = *(const uint4*)(Ahi + (long)(bm + ra0) * 256 + ua0 * 8);
        r1_ = *(const uint4*)(Ahi + (long)(bm + ra1) * 256 + ua1 * 8);
        r2_ = *(const uint4*)(Bhi + (long)(bn + ra0) * 256 + ua0 * 8);
        r3_ = *(const uint4*)(Bhi + (long)(bn + ra1) * 256 + ua1 * 8);
    }
    *(uint4*)&As[0][ra0 * 40 + ua0 * 8] = r0_;
    *(uint4*)&As[0][ra1 * 40 + ua1 * 8] = r1_;
    *(uint4*)&Bs[0][ra0 * 40 + ua0 * 8] = r2_;
    *(uint4*)&Bs[0][ra1 * 40 + ua1 * 8] = r3_;
    __syncthreads();

    for (int s = 0; s < 24; s++) {
        const int buf = s & 1;
        uint4 n0, n1, n2, n3;
        if (s < 23) {
            int sn = s + 1;
            int term = sn >> 3, k0 = (sn & 7) * 32;
            const __nv_bfloat16* Asrc = (term < 2) ? Ahi : Alo;
            const __nv_bfloat16* Bsrc = (term == 1) ? Blo : Bhi;
            n0 = *(const uint4*)(Asrc + (long)(bm + ra0) * 256 + k0 + ua0 * 8);
            n1 = *(const uint4*)(Asrc + (long)(bm + ra1) * 256 + k0 + ua1 * 8);
            n2 = *(const uint4*)(Bsrc + (long)(bn + ra0) * 256 + k0 + ua0 * 8);
            n3 = *(const uint4*)(Bsrc + (long)(bn + ra1) * 256 + k0 + ua1 * 8);
        }

        const __nv_bfloat16* Ab = As[buf];
        const __nv_bfloat16* Bb = Bs[buf];
#pragma unroll
        for (int k16 = 0; k16 < 2; k16++) {
            const int kb = k16 * 16;
            uint32_t af[4][4], bf[4][2];
#pragma unroll
            for (int mt = 0; mt < 4; mt++) {
                int rr = wm * 64 + mt * 16 + g;
                af[mt][0] = *(const uint32_t*)(Ab + rr * 40 + kb + 2 * t);
                af[mt][1] = *(const uint32_t*)(Ab + (rr + 8) * 40 + kb + 2 * t);
                af[mt][2] = *(const uint32_t*)(Ab + rr * 40 + kb + 8 + 2 * t);
                af[mt][3] = *(const uint32_t*)(Ab + (rr + 8) * 40 + kb + 8 + 2 * t);
            }
#pragma unroll
            for (int nt = 0; nt < 4; nt++) {
                int cc = wn * 32 + nt * 8 + g;
                bf[nt][0] = *(const uint32_t*)(Bb + cc * 40 + kb + 2 * t);
                bf[nt][1] = *(const uint32_t*)(Bb + cc * 40 + kb + 8 + 2 * t);
            }
#pragma unroll
            for (int mt = 0; mt < 4; mt++)
#pragma unroll
                for (int nt = 0; nt < 4; nt++)
                    asm volatile(
                        "mma.sync.aligned.m16n8k16.row.col.f32.bf16.bf16.f32 "
                        "{%0,%1,%2,%3}, {%4,%5,%6,%7}, {%8,%9}, {%0,%1,%2,%3};"
                        : "+f"(acc[mt][nt][0]), "+f"(acc[mt][nt][1]),
                          "+f"(acc[mt][nt][2]), "+f"(acc[mt][nt][3])
                        : "r"(af[mt][0]), "r"(af[mt][1]), "r"(af[mt][2]), "r"(af[mt][3]),
                          "r"(bf[nt][0]), "r"(bf[nt][1]));
        }

        if (s < 23) {
            const int nb = buf ^ 1;
            *(uint4*)&As[nb][ra0 * 40 + ua0 * 8] = n0;
            *(uint4*)&As[nb][ra1 * 40 + ua1 * 8] = n1;
            *(uint4*)&Bs[nb][ra0 * 40 + ua0 * 8] = n2;
            *(uint4*)&Bs[nb][ra1 * 40 + ua1 * 8] = n3;
        }
        __syncthreads();
    }

#pragma unroll
    for (int mt = 0; mt < 4; mt++) {
        long row0 = bm + wm * 64 + mt * 16 + g;
#pragma unroll
        for (int nt = 0; nt < 4; nt++) {
            int cl = wn * 32 + nt * 8 + 2 * t;
            float2 v0 = make_float2(acc[mt][nt][0] + bias_s[cl],
                                    acc[mt][nt][1] + bias_s[cl + 1]);
            float2 v1 = make_float2(acc[mt][nt][2] + bias_s[cl],
                                    acc[mt][nt][3] + bias_s[cl + 1]);
            *(float2*)(C + row0 * OUT_ + bn + cl)       = v0;
            *(float2*)(C + (row0 + 8) * OUT_ + bn + cl) = v1;
        }
    }
}

// ---------------- persistent GRU: R15 structure (split cluster barrier), FFMA2 dot -----
// Cluster of 8 CTAs per batch element; CTA c owns hidden units [c*32, c*32+32).
// Whh slice in SMEM (rows padded to 260 floats). h double-buffered; gate lanes multicast
// new h via st.shared::cluster. barrier.cluster SPLIT: arrive at end of step t, wait at
// top of step t+1. gi prefetched one step ahead. Dot uses fma.rn.f32x2 (same loads,
// same accumulation order, half the FMA issue slots).
__global__ void __launch_bounds__(128) __cluster_dims__(8, 1, 1)
gru_kernel(const float* __restrict__ gi, const float* __restrict__ Whh,
           const float* __restrict__ bhh, const int* __restrict__ lengths,
           const float* __restrict__ h0, float* __restrict__ outp, int ostride,
           float* __restrict__ hT, int T)
{
    extern __shared__ float sm[];
    float* Wsh  = sm;                 // 96*260
    float* hb0  = sm + 96 * 260;      // 256
    float* hb1  = hb0 + 256;          // 256
    float* gh_s = hb1 + 256;          // 96
    float* bg_s = gh_s + 96;          // 96

    const int c = blockIdx.x;         // cluster rank
    const int b = blockIdx.y;
    const int tid = threadIdx.x;
    const int len = lengths[b];

    for (int i = tid; i < 96 * 256; i += 128) {
        int r = i >> 8, k = i & 255;
        int grow = (r >> 5) * 256 + c * 32 + (r & 31);
        Wsh[r * 260 + k] = Whh[grow * 256 + k];
    }
    if (tid < 96) {
        int grow = (tid >> 5) * 256 + c * 32 + (tid & 31);
        bg_s[tid] = bhh[grow];
    }
    for (int j = tid; j < 256; j += 128)
        hb0[j] = h0 ? h0[b * 256 + j] : 0.f;

    asm volatile("barrier.cluster.arrive.aligned;\n" ::: "memory");
    asm volatile("barrier.cluster.wait.aligned;\n" ::: "memory");

    const int idx = c * 32 + (tid & 31);

    // prefetch gi for step 0
    float gir = 0.f, giz = 0.f, gin = 0.f;
    if (tid < 32) {
        long base = ((long)(b * T)) * 768;
        gir = gi[base + idx];
        giz = gi[base + 256 + idx];
        gin = gi[base + 512 + idx];
    }

    for (int t = 0; t < T; t++) {
        float* hcur = (t & 1) ? hb1 : hb0;
        float* hnxt = (t & 1) ? hb0 : hb1;

        if (t > 0)
            asm volatile("barrier.cluster.wait.aligned;\n" ::: "memory");

        if (tid < 96) {
            const ulonglong2* wr = (const ulonglong2*)(Wsh + tid * 260);
            const ulonglong2* hp = (const ulonglong2*)hcur;
            unsigned long long p0 = 0ull, p1 = 0ull;
#pragma unroll
            for (int k = 0; k < 64; k++) {
                ulonglong2 w = wr[k], h4 = hp[k];
                asm("fma.rn.f32x2 %0, %1, %2, %0;" : "+l"(p0) : "l"(w.x), "l"(h4.x));
                asm("fma.rn.f32x2 %0, %1, %2, %0;" : "+l"(p1) : "l"(w.y), "l"(h4.y));
            }
            float r0 = __uint_as_float((unsigned)p0) + __uint_as_float((unsigned)(p0 >> 32));
            float r1 = __uint_as_float((unsigned)p1) + __uint_as_float((unsigned)(p1 >> 32));
            gh_s[tid] = (r0 + r1) + bg_s[tid];
        }
        __syncthreads();

        if (tid < 32) {
            float rg = fsig(gir + gh_s[tid]);
            float zg = fsig(giz + gh_s[32 + tid]);
            float ng = ftanh(gin + rg * gh_s[64 + tid]);
            float hold = hcur[idx];
            float hnew = (1.f - zg) * ng + zg * hold;
            bool valid = (t < len);
            float hsel = valid ? hnew : hold;
            outp[((long)(b * T + t)) * ostride + idx] = valid ? hnew : 0.f;

            uint32_t laddr = su32(&hnxt[idx]);
#pragma unroll
            for (int tc = 0; tc < 8; tc++) {
                uint32_t raddr;
                asm volatile("mapa.shared::cluster.u32 %0, %1, %2;"
                             : "=r"(raddr) : "r"(laddr), "r"(tc));
                asm volatile("st.shared::cluster.f32 [%0], %1;"
                             :: "r"(raddr), "f"(hsel) : "memory");
            }
            // prefetch gi for step t+1 (issues before arrive; hides DRAM latency
            // under the next barrier wait + dot)
            if (t + 1 < T) {
                long base = ((long)(b * T + t + 1)) * 768;
                gir = gi[base + idx];
                giz = gi[base + 256 + idx];
                gin = gi[base + 512 + idx];
            }
        }
        asm volatile("barrier.cluster.arrive.aligned;\n" ::: "memory");
    }
    asm volatile("barrier.cluster.wait.aligned;\n" ::: "memory");

    if (hT && tid < 32) {
        float* hfin = (T & 1) ? hb1 : hb0;
        hT[b * 256 + idx] = hfin[idx];
    }
}

// ---------------- fused attention: energies -> softmax(valid) -> context ----------------
__global__ void __launch_bounds__(256)
attn_kernel(const float* __restrict__ Penc, const float* __restrict__ Pdec,
            const float* __restrict__ enc_out, const float* __restrict__ av,
            const float* __restrict__ avb, const int* __restrict__ elen_p,
            const int* __restrict__ dlen_p, float* __restrict__ cat)
{
    const int b = blockIdx.y, td = blockIdx.x;
    const int tid = threadIdx.x;
    const long row = (long)b * TD_ + td;

    if (td >= dlen_p[b]) {
        cat[row * 512 + 256 + tid] = 0.f;
        return;
    }
    __shared__ float Pd_s[256], v_s[256], e_s[128], red_s[16];
    Pd_s[tid] = Pdec[row * 256 + tid];
    v_s[tid]  = av[tid];
    const int elen = elen_p[b];
    const float vb = avb[0];
    __syncthreads();

    const int warp = tid >> 5, lane = tid & 31;
    for (int te = warp; te < elen; te += 8) {
        const float* pe = Penc + ((long)b * TE_ + te) * 256;
        float s = 0.f;
#pragma unroll
        for (int j = 0; j < 8; j++) {
            int h = lane + j * 32;
            s += ftanh(pe[h] + Pd_s[h]) * v_s[h];
        }
#pragma unroll
        for (int o = 16; o; o >>= 1) s += __shfl_xor_sync(0xffffffffu, s, o);
        if (lane == 0) e_s[te] = s + vb;
    }
    __syncthreads();

    float x = (tid < elen) ? e_s[tid] : -1e30f;
    float m = x;
#pragma unroll
    for (int o = 16; o; o >>= 1) m = fmaxf(m, __shfl_xor_sync(0xffffffffu, m, o));
    if (lane == 0) red_s[warp] = m;
    __syncthreads();
    float mx = red_s[0];
#pragma unroll
    for (int i = 1; i < 8; i++) mx = fmaxf(mx, red_s[i]);

    float p = (tid < elen) ? __expf(x - mx) : 0.f;
    float ps = p;
#pragma unroll
    for (int o = 16; o; o >>= 1) ps += __shfl_xor_sync(0xffffffffu, ps, o);
    if (lane == 0) red_s[8 + warp] = ps;
    __syncthreads();
    float sum = 0.f;
#pragma unroll
    for (int i = 0; i < 8; i++) sum += red_s[8 + i];
    float inv = __fdividef(1.f, sum);
    if (tid < 128) e_s[tid] = p * inv;
    __syncthreads();

    float acc = 0.f;
    const float* eo = enc_out + ((long)b * TE_) * 256 + tid;
    int te = 0;
    for (; te + 4 <= elen; te += 4) {
        acc += e_s[te]     * eo[(long)te * 256];
        acc += e_s[te + 1] * eo[(long)(te + 1) * 256];
        acc += e_s[te + 2] * eo[(long)(te + 2) * 256];
        acc += e_s[te + 3] * eo[(long)(te + 3) * 256];
    }
    for (; te < elen; te++) acc += e_s[te] * eo[(long)te * 256];
    cat[row * 512 + 256 + tid] = acc;
}

// ---------------- launch ----------------
extern "C" void kernel_launch(void* const* d_in, const int* in_sizes, int n_in,
                              void* d_out, int out_size)
{
    (void)in_sizes; (void)n_in; (void)out_size;
    const int*   enc_in  = (const int*)d_in[0];
    const int*   enc_len = (const int*)d_in[1];
    const int*   dec_in  = (const int*)d_in[2];
    const int*   dec_len = (const int*)d_in[3];
    const float* emb     = (const float*)d_in[4];
    const float* eWih = (const float*)d_in[5];
    const float* eWhh = (const float*)d_in[6];
    const float* ebih = (const float*)d_in[7];
    const float* ebhh = (const float*)d_in[8];
    const float* dWih = (const float*)d_in[9];
    const float* dWhh = (const float*)d_in[10];
    const float* dbih = (const float*)d_in[11];
    const float* dbhh = (const float*)d_in[12];
    const float* aW   = (const float*)d_in[13];
    const float* aWb  = (const float*)d_in[14];
    const float* av   = (const float*)d_in[15];
    const float* avb  = (const float*)d_in[16];
    const float* dnW  = (const float*)d_in[17];
    const float* dnb  = (const float*)d_in[18];
    const float* oW   = (const float*)d_in[19];
    const float* ob   = (const float*)d_in[20];
    float* out = (float*)d_out;

    float* S = nullptr;
    cudaGetSymbolAddress((void**)&S, g_scratch);
    __nv_bfloat16 *Ahi, *Alo, *Bhi, *Blo;
    cudaGetSymbolAddress((void**)&Ahi, g_Ahi);
    cudaGetSymbolAddress((void**)&Alo, g_Alo);
    cudaGetSymbolAddress((void**)&Bhi, g_Bhi);
    cudaGetSymbolAddress((void**)&Blo, g_Blo);

    float* enc_gi  = S;
    float* dec_gi  = S + 1572864;
    float* enc_out = S + 2359296;
    float* enc_hT  = S + 2883584;
    float* cat     = S + 2887680;
    float* Penc    = S + 3411968;
    float* Pdec    = S + 3936256;

    const size_t gru_smem = (96 * 260 + 256 + 256 + 96 + 96) * sizeof(float);  // ~102.7 KB
    cudaFuncSetAttribute(gru_kernel, cudaFuncAttributeMaxDynamicSharedMemorySize,
                         (int)gru_smem);

    // split out_W into bf16 hi/lo (independent; runs up front)
    split_kernel<<<(OUT_ * H_ / 4 + 255) / 256, 256>>>(oW, Bhi, Blo, OUT_ * H_ / 4);

    // gi pre-GEMMs (embedding gather fused), 64x64 tiles
    gemm_kernel<4, 4, 0, 0><<<dim3(12, 32), 256>>>(2048, 768, 256, emb, 256, enc_in,
                                                   eWih, 256, 0, ebih, enc_gi, 768,
                                                   nullptr, nullptr);
    gemm_kernel<4, 4, 0, 0><<<dim3(12, 16), 256>>>(1024, 768, 256, emb, 256, dec_in,
                                                   dWih, 256, 0, dbih, dec_gi, 768,
                                                   nullptr, nullptr);

    // encoder GRU (persistent, 16 clusters x 8 CTAs, split cluster barrier, FFMA2 dot)
    gru_kernel<<<dim3(8, 16), 128, gru_smem>>>(enc_gi, eWhh, ebhh, enc_len,
                                               nullptr, enc_out, 256, enc_hT, TE_);

    // Penc = enc_out @ attn_W[:, :256]^T
    gemm_kernel<4, 4, 0, 0><<<dim3(4, 32), 256>>>(2048, 256, 256, enc_out, 256, nullptr,
                                                  aW, 512, 0, nullptr, Penc, 256,
                                                  nullptr, nullptr);

    // decoder GRU -> cat[:, 0:256]
    gru_kernel<<<dim3(8, 16), 128, gru_smem>>>(dec_gi, dWhh, dbhh, dec_len,
                                               enc_hT, cat, 512, nullptr, TD_);

    // Pdec = dec_out @ attn_W[:, 256:512]^T + attn_Wb
    gemm_kernel<4, 4, 0, 0><<<dim3(4, 16), 256>>>(1024, 256, 256, cat, 512, nullptr,
                                                  aW, 512, 256, aWb, Pdec, 256,
                                                  nullptr, nullptr);

    // fused attention -> cat[:, 256:512]
    attn_kernel<<<dim3(TD_, B_), 256>>>(Penc, Pdec, enc_out, av, avb,
                                        enc_len, dec_len, cat);

    // dense = tanh(cat @ dense_W^T + dense_b), fused bf16 hi/lo split epilogue
    gemm_kernel<4, 4, 1, 1><<<dim3(4, 16), 256>>>(1024, 256, 512, cat, 512, nullptr,
                                                  dnW, 512, 0, dnb, nullptr, 256,
                                                  Ahi, Alo);

    // logits = dense @ out_W^T + out_b via bf16 mma.sync (3-term split)
    logits_mma_kernel<<<dim3(250, 8), 256>>>(Ahi, Alo, Bhi, Blo, ob, out);
}